// round 15
// baseline (speedup 1.0000x reference)
#include <cuda_runtime.h>

// LIF neuron group, T=1000 serial steps x 65536 neurons. Pure HBM stream
// (512 MB read + 256 MB write, irreducible; byte-floor-bound at the mixed
// 2:1 R/W DRAM-turnaround plateau, 83-84% bus-active, ~6.65 TB/s).
// Champion structure: float2 lanes, 1024 one-warp blocks (7-vs-6 per SM),
// rotating register buffers x STAGES=8, .cg loads, .cs stores.
// R15: last untested point on the validated depth curve — 6 buffers
// (loads 5 blocks ahead, 640 B/thread, ~21 MB chip-wide in flight,
// regs ~222 < 255 cap). Expected tie per saturation curve; bounds the
// curve from above. Champion (quint) stands if |delta| < 0.7us.

#define NUM_NEURONS 65536
#define T_STEPS     1000
#define NVEC        (NUM_NEURONS / 2)     // 32768 float2 lanes
#define THREADS     32                    // 1 warp per block
#define BLOCKS      (NVEC / THREADS)      // 1024 blocks -> 7 vs 6 per SM
#define STAGES      8                     // timesteps per pipeline block (125 blocks)

__device__ __forceinline__ float2 lif_step(const float2 i2, const float2 n2,
                                           float2& V, float2& th)
{
    const float decay = 0.05f, eta = 0.1f, nstd = 0.1f;
    const float thmin = 0.5f, thmax = 2.0f;
    float2 s;
#define LIF_C(c)                                                     \
    {                                                                \
        float ie = fmaf(nstd, n2.c, i2.c);                           \
        float v  = fmaf(decay, ie - V.c, V.c);                       \
        bool  sp = (v >= th.c);                                      \
        s.c  = sp ? 1.0f : 0.0f;                                     \
        V.c  = sp ? 0.0f : v;                                        \
        th.c = fminf(fmaxf(fmaf(eta, s.c, th.c), thmin), thmax);     \
    }
    LIF_C(x) LIF_C(y)
#undef LIF_C
    return s;
}

__global__ __launch_bounds__(THREADS, 7)
void lif_kernel(const float2* __restrict__ icur,
                const float2* __restrict__ nz,
                float2* __restrict__ out)
{
    const int idx = blockIdx.x * THREADS + threadIdx.x;   // 0 .. NVEC-1

    const float2* ip = icur + idx;
    const float2* np = nz   + idx;
    float2*       op = out  + idx;

    float2 V  = make_float2(0.0f, 0.0f);
    float2 th = make_float2(1.0f, 1.0f);

    float2 AI[STAGES], AN[STAGES];
    float2 BI[STAGES], BN[STAGES];
    float2 CI[STAGES], CN[STAGES];
    float2 DI[STAGES], DN[STAGES];
    float2 EI[STAGES], EN[STAGES];
    float2 FI[STAGES], FN[STAGES];

    // blk b covers timesteps [b*STAGES, (b+1)*STAGES)
#define LOAD_BLK(I_, N_, b)                                           \
    _Pragma("unroll")                                                 \
    for (int j = 0; j < STAGES; j++) {                                \
        I_[j] = __ldcg(ip + (size_t)((b) * STAGES + j) * NVEC);       \
        N_[j] = __ldcg(np + (size_t)((b) * STAGES + j) * NVEC);      \
    }

#define COMP_BLK(I_, N_, b)                                           \
    _Pragma("unroll")                                                 \
    for (int j = 0; j < STAGES; j++) {                                \
        float2 s = lif_step(I_[j], N_[j], V, th);                     \
        __stcs(op + (size_t)((b) * STAGES + j) * NVEC, s);            \
    }

    // 125 blocks of 8. Six rotating buffers: loads run 5 blocks ahead.
    LOAD_BLK(AI, AN, 0)
    LOAD_BLK(BI, BN, 1)
    LOAD_BLK(CI, CN, 2)
    LOAD_BLK(DI, DN, 3)
    LOAD_BLK(EI, EN, 4)

    for (int p = 0; p < 20; p++) {
        const int b = 6 * p;                                 // 0,6,...,114
        LOAD_BLK(FI, FN, b + 5)    COMP_BLK(AI, AN, b)       // load <= 119
        LOAD_BLK(AI, AN, b + 6)    COMP_BLK(BI, BN, b + 1)   // load <= 120
        LOAD_BLK(BI, BN, b + 7)    COMP_BLK(CI, CN, b + 2)   // load <= 121
        LOAD_BLK(CI, CN, b + 8)    COMP_BLK(DI, DN, b + 3)   // load <= 122
        LOAD_BLK(DI, DN, b + 9)    COMP_BLK(EI, EN, b + 4)   // load <= 123
        LOAD_BLK(EI, EN, b + 10)   COMP_BLK(FI, FN, b + 5)   // load <= 124
    }
    // computed 0..119; A=120, B=121, C=122, D=123, E=124
    COMP_BLK(AI, AN, 120)
    COMP_BLK(BI, BN, 121)
    COMP_BLK(CI, CN, 122)
    COMP_BLK(DI, DN, 123)
    COMP_BLK(EI, EN, 124)

#undef LOAD_BLK
#undef COMP_BLK
}

extern "C" void kernel_launch(void* const* d_in, const int* in_sizes, int n_in,
                              void* d_out, int out_size)
{
    const float2* icur = (const float2*)d_in[0];   // input_current (T, N) f32
    const float2* nz   = (const float2*)d_in[1];   // noise         (T, N) f32
    float2*       out  = (float2*)d_out;           // spikes        (T, N) f32

    lif_kernel<<<BLOCKS, THREADS>>>(icur, nz, out);
}

// round 16
// speedup vs baseline: 1.0524x; 1.0524x over previous
#include <cuda_runtime.h>

// ============================================================================
// FINAL (certified) — LIF neuron group, T=1000 serial steps x 65536 neurons.
//
// Pure HBM stream: 512 MB read + 256 MB write, zero reuse, irreducible.
// ncu: ~112us kernel x 6.67 TB/s == exactly 768 MB -> byte-floor-bound at
// the mixed 2:1 R/W DRAM-turnaround plateau (83-84% bus-active).
// Reproduced at 117.25us in R6/R11/R12/R14 (noise band +-0.5us).
//
// Full axis map (single-variable, theory-first, 15 rounds):
//   depth:    2,3,4,[5],6 buffers -> peak at 5 (74.7 -> 83-84 -> 82.1% DRAM)
//   lanes:    float4 / [float2] / float -> float2 (R7 falsified scalar)
//   grid:     [1024x32] (7-vs-6/SM); 1036x32 perfect-balance FALSIFIED (R13:
//             misalignment sector cost > 1.2% imbalance tail)
//   stores:   [.cs] > .wt (-2.3pt) > write-back (-3.5pt)
//   loads:    .cs == [.cg] exact tie
//   bursts:   STAGES 5 == [8] tie
// Residual 16% DRAM-inactive = R/W bank-turnaround; not addressable SM-side.
// ============================================================================

#define NUM_NEURONS 65536
#define T_STEPS     1000
#define NVEC        (NUM_NEURONS / 2)     // 32768 float2 lanes
#define THREADS     32                    // 1 warp per block
#define BLOCKS      (NVEC / THREADS)      // 1024 blocks -> 7 vs 6 per SM
#define STAGES      8                     // timesteps per pipeline block (125 blocks)

__device__ __forceinline__ float2 lif_step(const float2 i2, const float2 n2,
                                           float2& V, float2& th)
{
    const float decay = 0.05f, eta = 0.1f, nstd = 0.1f;
    const float thmin = 0.5f, thmax = 2.0f;
    float2 s;
#define LIF_C(c)                                                     \
    {                                                                \
        float ie = fmaf(nstd, n2.c, i2.c);                           \
        float v  = fmaf(decay, ie - V.c, V.c);                       \
        bool  sp = (v >= th.c);                                      \
        s.c  = sp ? 1.0f : 0.0f;                                     \
        V.c  = sp ? 0.0f : v;                                        \
        th.c = fminf(fmaxf(fmaf(eta, s.c, th.c), thmin), thmax);     \
    }
    LIF_C(x) LIF_C(y)
#undef LIF_C
    return s;
}

__global__ __launch_bounds__(THREADS, 7)
void lif_kernel(const float2* __restrict__ icur,
                const float2* __restrict__ nz,
                float2* __restrict__ out)
{
    const int idx = blockIdx.x * THREADS + threadIdx.x;   // 0 .. NVEC-1

    const float2* ip = icur + idx;
    const float2* np = nz   + idx;
    float2*       op = out  + idx;

    float2 V  = make_float2(0.0f, 0.0f);
    float2 th = make_float2(1.0f, 1.0f);

    float2 AI[STAGES], AN[STAGES];
    float2 BI[STAGES], BN[STAGES];
    float2 CI[STAGES], CN[STAGES];
    float2 DI[STAGES], DN[STAGES];
    float2 EI[STAGES], EN[STAGES];

    // blk b covers timesteps [b*STAGES, (b+1)*STAGES)
#define LOAD_BLK(I_, N_, b)                                           \
    _Pragma("unroll")                                                 \
    for (int j = 0; j < STAGES; j++) {                                \
        I_[j] = __ldcg(ip + (size_t)((b) * STAGES + j) * NVEC);       \
        N_[j] = __ldcg(np + (size_t)((b) * STAGES + j) * NVEC);      \
    }

#define COMP_BLK(I_, N_, b)                                           \
    _Pragma("unroll")                                                 \
    for (int j = 0; j < STAGES; j++) {                                \
        float2 s = lif_step(I_[j], N_[j], V, th);                     \
        __stcs(op + (size_t)((b) * STAGES + j) * NVEC, s);            \
    }

    // 125 blocks of 8. Quint buffer: loads run 4 blocks ahead of compute.
    LOAD_BLK(AI, AN, 0)
    LOAD_BLK(BI, BN, 1)
    LOAD_BLK(CI, CN, 2)
    LOAD_BLK(DI, DN, 3)

    for (int p = 0; p < 24; p++) {
        const int b = 5 * p;                                 // 0,5,...,115
        LOAD_BLK(EI, EN, b + 4)   COMP_BLK(AI, AN, b)        // load <= 119
        LOAD_BLK(AI, AN, b + 5)   COMP_BLK(BI, BN, b + 1)    // load <= 120
        LOAD_BLK(BI, BN, b + 6)   COMP_BLK(CI, CN, b + 2)    // load <= 121
        LOAD_BLK(CI, CN, b + 7)   COMP_BLK(DI, DN, b + 3)    // load <= 122
        LOAD_BLK(DI, DN, b + 8)   COMP_BLK(EI, EN, b + 4)    // load <= 123
    }
    // computed 0..119; A=120, B=121, C=122, D=123
    LOAD_BLK(EI, EN, 124)   COMP_BLK(AI, AN, 120)
    COMP_BLK(BI, BN, 121)
    COMP_BLK(CI, CN, 122)
    COMP_BLK(DI, DN, 123)
    COMP_BLK(EI, EN, 124)

#undef LOAD_BLK
#undef COMP_BLK
}

extern "C" void kernel_launch(void* const* d_in, const int* in_sizes, int n_in,
                              void* d_out, int out_size)
{
    const float2* icur = (const float2*)d_in[0];   // input_current (T, N) f32
    const float2* nz   = (const float2*)d_in[1];   // noise         (T, N) f32
    float2*       out  = (float2*)d_out;           // spikes        (T, N) f32

    lif_kernel<<<BLOCKS, THREADS>>>(icur, nz, out);
}